// round 8
// baseline (speedup 1.0000x reference)
#include <cuda_runtime.h>
#include <cstdint>

#define G    8192
#define P    24
#define NN   (G*P)          // 196608
#define EE   (NN*4)         // 786432
#define FIN  74
#define H1   32
#define H2   8
#define CAP  152            // per-group compact edge capacity
#define BCAP 32             // per-node bucket capacity
#define EPSBN 1e-5f

// ---------------- scratch ----------------
__device__ int      g_ndeg[NN];
__device__ unsigned g_bucket[(size_t)NN * BCAP];   // eid | s_loc<<20
__device__ unsigned g_csr[G * CAP];
__device__ int      g_gm[G];
__device__ float    g_xl[(size_t)NN * H1];
__device__ float    g_xr[(size_t)NN * H1];
__device__ float    g_eaWe2[(size_t)G * CAP * H2];
__device__ float    g_selfWe2[(size_t)NN * H2];
__device__ float    g_h1[(size_t)NN * H1];
__device__ float    g_h2[(size_t)NN * H2];
__device__ double   g_sum1[H1], g_sq1[H1], g_sum2[H2], g_sq2[H2];

// ---------------- K0: zero node counters + stats ----------------
__global__ void kZero() {
    int i = blockIdx.x * blockDim.x + threadIdx.x;
    if (i < NN) g_ndeg[i] = 0;
    if (blockIdx.x == 0) {
        int t = threadIdx.x;
        if (t < H1) { g_sum1[t] = 0.0; g_sq1[t] = 0.0; }
        if (t < H2) { g_sum2[t] = 0.0; g_sq2[t] = 0.0; }
    }
}

// ---------------- K1: scatter into per-dst-node buckets ----------------
__global__ void kScatter(const int* __restrict__ ei) {
    int e = blockIdx.x * blockDim.x + threadIdx.x;
    if (e >= EE) return;
    int s = ei[e], d = ei[EE + e];
    int pos = atomicAdd(&g_ndeg[d], 1);
    if (pos < BCAP)
        g_bucket[(size_t)d * BCAP + pos] = (unsigned)e | ((unsigned)(s % P) << 20);
}

// ============ dense node GEMV — float4 k-blocked ============
__global__ __launch_bounds__(256) void kXlXr(
    const float* __restrict__ x,
    const float* __restrict__ Wl1, const float* __restrict__ bl1,
    const float* __restrict__ Wr1, const float* __restrict__ br1)
{
    __shared__ float2 sW[FIN * H1];
    __shared__ float  sx[64 * 76];
    int t = threadIdx.x, lane = t & 31, wid = t >> 5;
    int n0 = blockIdx.x * 64;

    for (int i = t; i < FIN * H1; i += 256)
        sW[i] = make_float2(Wl1[i], Wr1[i]);
    for (int i = t; i < 64 * 19; i += 256) {
        int r = i / 19, q = i - r * 19;
        ((float4*)(sx + r * 76))[q] = ((const float4*)(x + (size_t)(n0 + r) * 96))[q];
    }
    __syncthreads();

    float bl = bl1[lane], br = br1[lane];
    float al[8], ar[8];
#pragma unroll
    for (int n = 0; n < 8; n++) { al[n] = bl; ar[n] = br; }

    const float* xbase = sx + wid * 8 * 76;
#pragma unroll 1
    for (int k4 = 0; k4 < 18; k4++) {
        int k = k4 * 4;
        float2 w0 = sW[(k + 0) * H1 + lane];
        float2 w1 = sW[(k + 1) * H1 + lane];
        float2 w2 = sW[(k + 2) * H1 + lane];
        float2 w3 = sW[(k + 3) * H1 + lane];
#pragma unroll
        for (int n = 0; n < 8; n++) {
            float4 xv = *(const float4*)(xbase + n * 76 + k);
            al[n] += xv.x * w0.x + xv.y * w1.x + xv.z * w2.x + xv.w * w3.x;
            ar[n] += xv.x * w0.y + xv.y * w1.y + xv.z * w2.y + xv.w * w3.y;
        }
    }
    {
        float2 w0 = sW[72 * H1 + lane];
        float2 w1 = sW[73 * H1 + lane];
#pragma unroll
        for (int n = 0; n < 8; n++) {
            float2 xv = *(const float2*)(xbase + n * 76 + 72);
            al[n] += xv.x * w0.x + xv.y * w1.x;
            ar[n] += xv.x * w0.y + xv.y * w1.y;
        }
    }
#pragma unroll
    for (int n = 0; n < 8; n++) {
        size_t idx = (size_t)(n0 + wid * 8 + n) * H1 + lane;
        g_xl[idx] = al[n];
        g_xr[idx] = ar[n];
    }
}

// ============ K2: GATv2 layer 1 — fused dedup'd edge phase ============
__global__ __launch_bounds__(256) void kA(
    const float* __restrict__ ea,
    const float* __restrict__ We1, const float* __restrict__ att1,
    const float* __restrict__ bo1, const float* __restrict__ We2)
{
    int g = blockIdx.x;
    int t = threadIdx.x, lane = t & 31, wid = t >> 5;

    __shared__ float sWe1[16 * H1];             // plain [k][o]
    __shared__ float sWe2[16 * H2];             // plain [k][o]
    __shared__ float satt[H1], sbo[H1];
    __shared__ float sxl[P * 36], sxr[P * 36];
    __shared__ float sa1[CAP * 36];             // cols 0..31 a1, col 32 logit/w
    __shared__ float sea[CAP * 16];
    __shared__ float ssum2[P * H2];
    __shared__ unsigned scsr[CAP];
    __shared__ int sdegc[P], sstart[P], sm_m[1];
    __shared__ float sred[256];

    // ---- phase 1: loads
    for (int i = t; i < 16 * H1; i += 256) sWe1[i] = We1[i];
    if (t < 16 * H2) sWe2[t] = We2[t];
    if (t < H1) { satt[t] = att1[t]; sbo[t] = bo1[t]; }
    for (int i = t; i < P * H1 / 4; i += 256) {
        int n = i >> 3, q = i & 7;
        ((float4*)(sxl + n * 36))[q] = ((const float4*)(g_xl + (size_t)g * P * H1))[i];
        ((float4*)(sxr + n * 36))[q] = ((const float4*)(g_xr + (size_t)g * P * H1))[i];
    }
    if (t < P) {
        int d = g_ndeg[g * P + t];
        sdegc[t] = d > BCAP ? BCAP : d;
    }
    if (t < P * H2) ssum2[t] = 0.f;
    __syncthreads();

    // ---- phase 2: warp-scan CSR starts
    if (wid == 0) {
        int v = (lane < P) ? sdegc[lane] : 0;
        int orig = v;
#pragma unroll
        for (int off = 1; off < 32; off <<= 1) {
            int u = __shfl_up_sync(0xffffffffu, v, off);
            if (lane >= off) v += u;
        }
        if (lane < P) sstart[lane] = v - orig;
        if (lane == P - 1) { sm_m[0] = v; g_gm[g] = v; }
    }
    __syncthreads();

    int base = g * CAP;
    int m = sm_m[0]; if (m > CAP) m = CAP;

    // ---- phase 3: compact copy from node buckets
    for (int n = wid; n < P; n += 8) {
        int deg = sdegc[n], st = sstart[n];
        if (lane < deg) {
            unsigned pk = g_bucket[(size_t)(g * P + n) * BCAP + lane]
                        | ((unsigned)n << 25);
            scsr[st + lane] = pk;
            g_csr[base + st + lane] = pk;
        }
    }
    __syncthreads();

    // ---- phase 4: ea prefetch (float4)
    for (int idx = t; idx < m * 4; idx += 256) {
        int j = idx >> 2, q = idx & 3;
        int eid = scsr[j] & 0xFFFFF;
        ((float4*)sea)[j * 4 + q] = ((const float4*)ea)[eid * 4 + q];
    }
    __syncthreads();

    // ---- phase 5 (fused): thread-per-(edge, quad): a1, a2, logit
    {
        int oq = t & 7;
        unsigned omask = 0xFFu << ((lane >> 3) * 8);
        const float4* W14 = (const float4*)sWe1;   // index k*8 + oq
        const float4* W24 = (const float4*)sWe2;   // index k*2 + oq
        for (int j0 = 0; j0 < m; j0 += 32) {
            int j = j0 + (t >> 3);
            if (j < m) {
                unsigned pk = scsr[j];
                int s = (pk >> 20) & 31, d = (pk >> 25) & 31;
                float ev[16];
                *(float4*)(ev)      = ((const float4*)(sea + j * 16))[0];
                *(float4*)(ev + 4)  = ((const float4*)(sea + j * 16))[1];
                *(float4*)(ev + 8)  = ((const float4*)(sea + j * 16))[2];
                *(float4*)(ev + 12) = ((const float4*)(sea + j * 16))[3];
                float4 a = make_float4(0.f, 0.f, 0.f, 0.f);
#pragma unroll
                for (int k = 0; k < 16; k++) {
                    float4 w = W14[k * 8 + oq];
                    a.x += ev[k] * w.x; a.y += ev[k] * w.y;
                    a.z += ev[k] * w.z; a.w += ev[k] * w.w;
                }
                if (oq < 2) {
                    float4 b = make_float4(0.f, 0.f, 0.f, 0.f);
#pragma unroll
                    for (int k = 0; k < 16; k++) {
                        float4 w = W24[k * 2 + oq];
                        b.x += ev[k] * w.x; b.y += ev[k] * w.y;
                        b.z += ev[k] * w.z; b.w += ev[k] * w.w;
                    }
                    *(float4*)(&g_eaWe2[(size_t)(base + j) * H2 + oq * 4]) = b;
                    atomicAdd(&ssum2[d * H2 + oq * 4 + 0], b.x);
                    atomicAdd(&ssum2[d * H2 + oq * 4 + 1], b.y);
                    atomicAdd(&ssum2[d * H2 + oq * 4 + 2], b.z);
                    atomicAdd(&ssum2[d * H2 + oq * 4 + 3], b.w);
                }
                float4 xlv = *(const float4*)(sxl + s * 36 + oq * 4);
                float4 xrv = *(const float4*)(sxr + d * 36 + oq * 4);
                float4 atv = *(const float4*)(satt + oq * 4);
                float m0 = xlv.x + xrv.x + a.x, m1 = xlv.y + xrv.y + a.y;
                float m2 = xlv.z + xrv.z + a.z, m3 = xlv.w + xrv.w + a.w;
                float e = (m0 > 0.f ? m0 : 0.2f * m0) * atv.x
                        + (m1 > 0.f ? m1 : 0.2f * m1) * atv.y
                        + (m2 > 0.f ? m2 : 0.2f * m2) * atv.z
                        + (m3 > 0.f ? m3 : 0.2f * m3) * atv.w;
                e += __shfl_xor_sync(omask, e, 1);
                e += __shfl_xor_sync(omask, e, 2);
                e += __shfl_xor_sync(omask, e, 4);
                *(float4*)(sa1 + j * 36 + oq * 4) = a;
                if (oq == 0) sa1[j * 36 + 32] = e;
            }
        }
    }
    __syncthreads();

    // ---- phase 6: per-node softmax + aggregation (warp per node)
    float st_s = 0.f, st_q = 0.f;
    for (int n = wid; n < P; n += 8) {
        int st = sstart[n], deg = sdegc[n];
        float invd = 1.f / fmaxf((float)deg, 1.f);
        float xln = sxl[n * 36 + lane], xrn = sxr[n * 36 + lane];
        float sum1 = 0.f;
        for (int j = st; j < st + deg; j++) sum1 += sa1[j * 36 + lane];
        float mvs = xln + xrn + sum1 * invd;
        float lrs = mvs > 0.f ? mvs : 0.2f * mvs;
        float eps_ = lrs * satt[lane];
#pragma unroll
        for (int o = 16; o; o >>= 1) eps_ += __shfl_xor_sync(0xffffffffu, eps_, o);
        if (lane < 8)
            g_selfWe2[(size_t)(g * P + n) * H2 + lane] = ssum2[n * H2 + lane] * invd;
        float el = (lane < deg) ? sa1[(st + lane) * 36 + 32] : -1e30f;
        float mx = el;
#pragma unroll
        for (int o = 16; o; o >>= 1) mx = fmaxf(mx, __shfl_xor_sync(0xffffffffu, mx, o));
        mx = fmaxf(mx, eps_);
        float wj = (lane < deg) ? __expf(el - mx) : 0.f;
        float denom = wj;
#pragma unroll
        for (int o = 16; o; o >>= 1) denom += __shfl_xor_sync(0xffffffffu, denom, o);
        float wself = __expf(eps_ - mx);
        denom += wself;
        if (lane < deg) sa1[(st + lane) * 36 + 32] = wj;
        __syncwarp();
        float acc = wself * xln;
        for (int j = st; j < st + deg; j++) {
            int s = (scsr[j] >> 20) & 31;
            acc += sa1[j * 36 + 32] * sxl[s * 36 + lane];
        }
        float ov = acc / denom + sbo[lane];
        ov = fmaxf(ov, 0.f);
        g_h1[(size_t)(g * P + n) * H1 + lane] = ov;
        st_s += ov; st_q += ov * ov;
    }

    // ---- phase 7: fused BN1 stats
    sred[t] = st_s; __syncthreads();
    if (t < 32) {
        float a = 0.f;
#pragma unroll
        for (int k = 0; k < 8; k++) a += sred[t + 32 * k];
        atomicAdd(&g_sum1[t], (double)a);
    }
    __syncthreads();
    sred[t] = st_q; __syncthreads();
    if (t < 32) {
        float a = 0.f;
#pragma unroll
        for (int k = 0; k < 8; k++) a += sred[t + 32 * k];
        atomicAdd(&g_sq1[t], (double)a);
    }
}

// ============ K3: GATv2 layer 2 ============
__global__ __launch_bounds__(192) void kC(
    const float* __restrict__ Wl2, const float* __restrict__ bl2,
    const float* __restrict__ Wr2, const float* __restrict__ br2,
    const float* __restrict__ att2, const float* __restrict__ bo2,
    const float* __restrict__ g1v, const float* __restrict__ be1)
{
    int g = blockIdx.x;
    int t = threadIdx.x, lane = t & 31;
    int n = t >> 3, l = t & 7;
    unsigned omask = 0xFFu << ((lane >> 3) * 8);

    __shared__ float sh[P * 33];
    __shared__ float sWl[H1 * H2], sWr[H1 * H2];
    __shared__ float sxl[P * 9], sxr[P * 9];
    __shared__ float sa2[CAP * 9];
    __shared__ unsigned scsr[CAP];
    __shared__ float sscale[H1], sbias[H1], satt[H2], sbl[H2], sbr[H2], sbo[H2];
    __shared__ int sdegc[P], sstart[P];
    __shared__ float sred[192];

    if (t < H1) {
        double mu = g_sum1[t] / (double)NN;
        double var = g_sq1[t] / (double)NN - mu * mu;
        float sc = g1v[t] * rsqrtf((float)var + EPSBN);
        sscale[t] = sc;
        sbias[t] = be1[t] - (float)mu * sc;
    }
    for (int i = t; i < H1 * H2; i += 192) { sWl[i] = Wl2[i]; sWr[i] = Wr2[i]; }
    if (t < H2) { satt[t] = att2[t]; sbl[t] = bl2[t]; sbr[t] = br2[t]; sbo[t] = bo2[t]; }
    if (t < P) {
        int d = g_ndeg[g * P + t];
        sdegc[t] = d > BCAP ? BCAP : d;
    }
    __syncthreads();

    int base = g * CAP;
    int m = g_gm[g]; if (m > CAP) m = CAP;

    for (int i = t; i < P * H1; i += 192) {
        int nn = i >> 5, k = i & 31;
        sh[nn * 33 + k] = g_h1[(size_t)g * P * H1 + i] * sscale[k] + sbias[k];
    }
    for (int i = t; i < m; i += 192) scsr[i] = g_csr[base + i];
    for (int i = t; i < m * 2; i += 192) {
        float4 v = ((const float4*)g_eaWe2)[(size_t)base * 2 + i];
        int j = i >> 1, half = (i & 1) * 4;
        sa2[j * 9 + half + 0] = v.x;
        sa2[j * 9 + half + 1] = v.y;
        sa2[j * 9 + half + 2] = v.z;
        sa2[j * 9 + half + 3] = v.w;
    }
    if (t < 32) {
        int v = (lane < P) ? sdegc[lane] : 0;
        int orig = v;
#pragma unroll
        for (int off = 1; off < 32; off <<= 1) {
            int u = __shfl_up_sync(0xffffffffu, v, off);
            if (lane >= off) v += u;
        }
        if (lane < P) sstart[lane] = v - orig;
    }
    __syncthreads();

    {
        float al = sbl[l], ar = sbr[l];
#pragma unroll
        for (int k = 0; k < H1; k++) {
            float v = sh[n * 33 + k];
            al += v * sWl[k * H2 + l];
            ar += v * sWr[k * H2 + l];
        }
        sxl[n * 9 + l] = al; sxr[n * 9 + l] = ar;
    }
    __syncthreads();

    if (t < m) {
        unsigned pk = scsr[t];
        int s = (pk >> 20) & 31, d = (pk >> 25) & 31;
        float e = 0.f;
#pragma unroll
        for (int k = 0; k < H2; k++) {
            float mv = sxl[s * 9 + k] + sxr[d * 9 + k] + sa2[t * 9 + k];
            float lr = mv > 0.f ? mv : 0.2f * mv;
            e += lr * satt[k];
        }
        sa2[t * 9 + 8] = e;
    }
    __syncthreads();

    int st = sstart[n], deg = sdegc[n];
    float xln = sxl[n * 9 + l], xrn = sxr[n * 9 + l];
    float mvs = xln + xrn + g_selfWe2[(size_t)g * P * H2 + t];
    float lrs = mvs > 0.f ? mvs : 0.2f * mvs;
    float eps_ = lrs * satt[l];
    eps_ += __shfl_xor_sync(omask, eps_, 1);
    eps_ += __shfl_xor_sync(omask, eps_, 2);
    eps_ += __shfl_xor_sync(omask, eps_, 4);
    float mx = -1e30f;
    for (int j = st + l; j < st + deg; j += 8) mx = fmaxf(mx, sa2[j * 9 + 8]);
    mx = fmaxf(mx, __shfl_xor_sync(omask, mx, 1));
    mx = fmaxf(mx, __shfl_xor_sync(omask, mx, 2));
    mx = fmaxf(mx, __shfl_xor_sync(omask, mx, 4));
    mx = fmaxf(mx, eps_);
    float denom = 0.f;
    for (int j = st + l; j < st + deg; j += 8) {
        float w = __expf(sa2[j * 9 + 8] - mx);
        sa2[j * 9 + 8] = w;
        denom += w;
    }
    denom += __shfl_xor_sync(omask, denom, 1);
    denom += __shfl_xor_sync(omask, denom, 2);
    denom += __shfl_xor_sync(omask, denom, 4);
    float wself = __expf(eps_ - mx);
    denom += wself;
    __syncwarp();
    float acc = wself * xln;
    for (int j = st; j < st + deg; j++) {
        int s = (scsr[j] >> 20) & 31;
        acc += sa2[j * 9 + 8] * sxl[s * 9 + l];
    }
    float ov = acc / denom + sbo[l];
    ov = 1.f / (1.f + __expf(-ov));
    g_h2[(size_t)g * P * H2 + t] = ov;

    sred[t] = ov; __syncthreads();
    if (t < 8) {
        float a = 0.f;
#pragma unroll
        for (int k = 0; k < 24; k++) a += sred[t + 8 * k];
        atomicAdd(&g_sum2[t], (double)a);
    }
    __syncthreads();
    sred[t] = ov * ov; __syncthreads();
    if (t < 8) {
        float a = 0.f;
#pragma unroll
        for (int k = 0; k < 24; k++) a += sred[t + 8 * k];
        atomicAdd(&g_sq2[t], (double)a);
    }
}

// ============ K4: BN2 + pool + MLP head ============
__global__ __launch_bounds__(256) void kE(
    const float* __restrict__ x,
    const float* __restrict__ g2, const float* __restrict__ be2,
    const float* __restrict__ W1, const float* __restrict__ b1,
    const float* __restrict__ W2, const float* __restrict__ b2,
    const float* __restrict__ W3, const float* __restrict__ b3,
    const float* __restrict__ W4, const float* __restrict__ b4,
    const float* __restrict__ Wo, const float* __restrict__ bo,
    float* __restrict__ out)
{
    int t = threadIdx.x, w = t >> 5, lane = t & 31;
    int g = blockIdx.x * 8 + w;

    __shared__ float sW1[30 * 32], sb1[32], sW2[32 * 16], sb2[16];
    __shared__ float sW3[16 * 8], sb3[8], sW4[8 * 4], sb4[4], sWo[4 * 2], sbo[2];
    __shared__ float sscale[H2], sbias[H2];
    __shared__ float zz[8][90];

    for (int i = t; i < 30 * 32; i += 256) sW1[i] = W1[i];
    for (int i = t; i < 32 * 16; i += 256) sW2[i] = W2[i];
    if (t < 16 * 8) sW3[t] = W3[t];
    if (t < 8 * 4) sW4[t] = W4[t];
    if (t < 8) sWo[t] = Wo[t];
    if (t < 32) sb1[t] = b1[t];
    if (t < 16) sb2[t] = b2[t];
    if (t < 8) sb3[t] = b3[t];
    if (t < 4) sb4[t] = b4[t];
    if (t < 2) sbo[t] = bo[t];
    if (t < H2) {
        double mu = g_sum2[t] / (double)NN;
        double var = g_sq2[t] / (double)NN - mu * mu;
        float sc = g2[t] * rsqrtf((float)var + EPSBN);
        sscale[t] = sc;
        sbias[t] = be2[t] - (float)mu * sc;
    }
    __syncthreads();

    float* z  = zz[w];
    float* z1 = z + 30;
    float* z2 = z1 + 32;
    float* z3 = z2 + 16;
    float* z4 = z3 + 8;

    float acc = 0.f;
    for (int j = lane; j < P * H2; j += 32) {
        int f = j & 7;
        acc += g_h2[(size_t)g * P * H2 + j] * sscale[f] + sbias[f];
    }
    acc += __shfl_xor_sync(0xffffffffu, acc, 8);
    acc += __shfl_xor_sync(0xffffffffu, acc, 16);
    if (lane < 8)  z[lane] = acc * (1.f / 24.f);
    if (lane < 22) z[8 + lane] = x[(size_t)(g * P) * 96 + 74 + lane];
    __syncwarp();

    { float a = sb1[lane];
#pragma unroll
      for (int k = 0; k < 30; k++) a += z[k] * sW1[k * 32 + lane];
      z1[lane] = fmaxf(a, 0.f); }
    __syncwarp();
    if (lane < 16) { float a = sb2[lane];
#pragma unroll
      for (int k = 0; k < 32; k++) a += z1[k] * sW2[k * 16 + lane];
      z2[lane] = fmaxf(a, 0.f); }
    __syncwarp();
    if (lane < 8) { float a = sb3[lane];
#pragma unroll
      for (int k = 0; k < 16; k++) a += z2[k] * sW3[k * 8 + lane];
      z3[lane] = fmaxf(a, 0.f); }
    __syncwarp();
    if (lane < 4) { float a = sb4[lane];
#pragma unroll
      for (int k = 0; k < 8; k++) a += z3[k] * sW4[k * 4 + lane];
      z4[lane] = fmaxf(a, 0.f); }
    __syncwarp();
    if (lane < 2) { float a = sbo[lane];
#pragma unroll
      for (int k = 0; k < 4; k++) a += z4[k] * sWo[k * 2 + lane];
      out[g * 2 + lane] = a; }
}

// ---------------- launch ----------------
extern "C" void kernel_launch(void* const* d_in, const int* in_sizes, int n_in,
                              void* d_out, int out_size)
{
    const float* x    = (const float*)d_in[0];
    const int*   ei   = (const int*)  d_in[1];
    const float* ea   = (const float*)d_in[2];
    const float* Wl1  = (const float*)d_in[4];
    const float* bl1  = (const float*)d_in[5];
    const float* Wr1  = (const float*)d_in[6];
    const float* br1  = (const float*)d_in[7];
    const float* We1  = (const float*)d_in[8];
    const float* att1 = (const float*)d_in[9];
    const float* bo1  = (const float*)d_in[10];
    const float* Wl2  = (const float*)d_in[11];
    const float* bl2  = (const float*)d_in[12];
    const float* Wr2  = (const float*)d_in[13];
    const float* br2  = (const float*)d_in[14];
    const float* We2  = (const float*)d_in[15];
    const float* att2 = (const float*)d_in[16];
    const float* bo2  = (const float*)d_in[17];
    const float* g1   = (const float*)d_in[18];
    const float* be1  = (const float*)d_in[19];
    const float* g2   = (const float*)d_in[20];
    const float* be2  = (const float*)d_in[21];
    const float* fc1W = (const float*)d_in[22];
    const float* fc1b = (const float*)d_in[23];
    const float* fc2W = (const float*)d_in[24];
    const float* fc2b = (const float*)d_in[25];
    const float* fc3W = (const float*)d_in[26];
    const float* fc3b = (const float*)d_in[27];
    const float* fc4W = (const float*)d_in[28];
    const float* fc4b = (const float*)d_in[29];
    const float* outW = (const float*)d_in[30];
    const float* outb = (const float*)d_in[31];

    kZero<<<NN / 256, 256>>>();
    kScatter<<<EE / 256, 256>>>(ei);
    kXlXr<<<NN / 64, 256>>>(x, Wl1, bl1, Wr1, br1);
    kA<<<G, 256>>>(ea, We1, att1, bo1, We2);
    kC<<<G, 192>>>(Wl2, bl2, Wr2, br2, att2, bo2, g1, be1);
    kE<<<G / 8, 256>>>(x, g2, be2, fc1W, fc1b, fc2W, fc2b, fc3W, fc3b,
                       fc4W, fc4b, outW, outb, (float*)d_out);
}

// round 9
// speedup vs baseline: 1.0331x; 1.0331x over previous
#include <cuda_runtime.h>
#include <cstdint>

#define G    8192
#define P    24
#define NN   (G*P)          // 196608
#define EE   (NN*4)         // 786432
#define FIN  74
#define H1   32
#define H2   8
#define CAP  152            // per-group compact edge capacity
#define BCAP 32             // per-node bucket capacity
#define EPSBN 1e-5f

// ---------------- scratch ----------------
__device__ int      g_ndeg[NN];
__device__ unsigned g_bucket[(size_t)NN * BCAP];   // eid | s_loc<<20
__device__ unsigned g_csr[G * CAP];
__device__ int      g_gm[G];
__device__ float    g_xl[(size_t)NN * H1];
__device__ float    g_xr[(size_t)NN * H1];
__device__ float    g_eaWe2[(size_t)G * CAP * H2];
__device__ float    g_selfWe2[(size_t)NN * H2];
__device__ float    g_h1[(size_t)NN * H1];
__device__ float    g_h2[(size_t)NN * H2];
__device__ double   g_sum1[H1], g_sq1[H1], g_sum2[H2], g_sq2[H2];

// ---------------- K0: zero node counters + stats ----------------
__global__ void kZero() {
    int i = blockIdx.x * blockDim.x + threadIdx.x;
    if (i < NN) g_ndeg[i] = 0;
    if (blockIdx.x == 0) {
        int t = threadIdx.x;
        if (t < H1) { g_sum1[t] = 0.0; g_sq1[t] = 0.0; }
        if (t < H2) { g_sum2[t] = 0.0; g_sq2[t] = 0.0; }
    }
}

// ---------------- K1: scatter into per-dst-node buckets ----------------
__global__ void kScatter(const int* __restrict__ ei) {
    int e = blockIdx.x * blockDim.x + threadIdx.x;
    if (e >= EE) return;
    int s = ei[e], d = ei[EE + e];
    int pos = atomicAdd(&g_ndeg[d], 1);
    if (pos < BCAP)
        g_bucket[(size_t)d * BCAP + pos] = (unsigned)e | ((unsigned)(s % P) << 20);
}

// ============ dense node GEMV — float4 k-blocked ============
__global__ __launch_bounds__(256) void kXlXr(
    const float* __restrict__ x,
    const float* __restrict__ Wl1, const float* __restrict__ bl1,
    const float* __restrict__ Wr1, const float* __restrict__ br1)
{
    __shared__ float2 sW[FIN * H1];
    __shared__ float  sx[64 * 76];
    int t = threadIdx.x, lane = t & 31, wid = t >> 5;
    int n0 = blockIdx.x * 64;

    for (int i = t; i < FIN * H1; i += 256)
        sW[i] = make_float2(Wl1[i], Wr1[i]);
    for (int i = t; i < 64 * 19; i += 256) {
        int r = i / 19, q = i - r * 19;
        ((float4*)(sx + r * 76))[q] = ((const float4*)(x + (size_t)(n0 + r) * 96))[q];
    }
    __syncthreads();

    float bl = bl1[lane], br = br1[lane];
    float al[8], ar[8];
#pragma unroll
    for (int n = 0; n < 8; n++) { al[n] = bl; ar[n] = br; }

    const float* xbase = sx + wid * 8 * 76;
#pragma unroll 1
    for (int k4 = 0; k4 < 18; k4++) {
        int k = k4 * 4;
        float2 w0 = sW[(k + 0) * H1 + lane];
        float2 w1 = sW[(k + 1) * H1 + lane];
        float2 w2 = sW[(k + 2) * H1 + lane];
        float2 w3 = sW[(k + 3) * H1 + lane];
#pragma unroll
        for (int n = 0; n < 8; n++) {
            float4 xv = *(const float4*)(xbase + n * 76 + k);
            al[n] += xv.x * w0.x + xv.y * w1.x + xv.z * w2.x + xv.w * w3.x;
            ar[n] += xv.x * w0.y + xv.y * w1.y + xv.z * w2.y + xv.w * w3.y;
        }
    }
    {
        float2 w0 = sW[72 * H1 + lane];
        float2 w1 = sW[73 * H1 + lane];
#pragma unroll
        for (int n = 0; n < 8; n++) {
            float2 xv = *(const float2*)(xbase + n * 76 + 72);
            al[n] += xv.x * w0.x + xv.y * w1.x;
            ar[n] += xv.x * w0.y + xv.y * w1.y;
        }
    }
#pragma unroll
    for (int n = 0; n < 8; n++) {
        size_t idx = (size_t)(n0 + wid * 8 + n) * H1 + lane;
        g_xl[idx] = al[n];
        g_xr[idx] = ar[n];
    }
}

// ============ K2: GATv2 layer 1 — slim smem via sumEA linearity ============
__global__ __launch_bounds__(256, 6) void kA(
    const float* __restrict__ ea,
    const float* __restrict__ We1, const float* __restrict__ att1,
    const float* __restrict__ bo1, const float* __restrict__ We2)
{
    int g = blockIdx.x;
    int t = threadIdx.x, lane = t & 31, wid = t >> 5;

    __shared__ float sWe1[16 * H1];             // [k][o]
    __shared__ float sWe2[16 * H2];             // [k][o]
    __shared__ float satt[H1], sbo[H1];
    __shared__ float sxl[P * 36], sxr[P * 36];
    __shared__ float sea[CAP * 16];
    __shared__ float ssumEA[P * 16];            // Σ ea over in-edges, per node
    __shared__ float se[CAP];                   // logit → softmax weight
    __shared__ unsigned scsr[CAP];
    __shared__ int sdegc[P], sstart[P], sm_m[1];
    __shared__ float sred[256];

    // ---- phase 1: loads
    for (int i = t; i < 16 * H1; i += 256) sWe1[i] = We1[i];
    if (t < 16 * H2) sWe2[t] = We2[t];
    if (t < H1) { satt[t] = att1[t]; sbo[t] = bo1[t]; }
    for (int i = t; i < P * H1 / 4; i += 256) {
        int n = i >> 3, q = i & 7;
        ((float4*)(sxl + n * 36))[q] = ((const float4*)(g_xl + (size_t)g * P * H1))[i];
        ((float4*)(sxr + n * 36))[q] = ((const float4*)(g_xr + (size_t)g * P * H1))[i];
    }
    if (t < P) {
        int d = g_ndeg[g * P + t];
        sdegc[t] = d > BCAP ? BCAP : d;
    }
    for (int i = t; i < P * 16; i += 256) ssumEA[i] = 0.f;
    __syncthreads();

    // ---- phase 2: warp-scan CSR starts
    if (wid == 0) {
        int v = (lane < P) ? sdegc[lane] : 0;
        int orig = v;
#pragma unroll
        for (int off = 1; off < 32; off <<= 1) {
            int u = __shfl_up_sync(0xffffffffu, v, off);
            if (lane >= off) v += u;
        }
        if (lane < P) sstart[lane] = v - orig;
        if (lane == P - 1) { sm_m[0] = v; g_gm[g] = v; }
    }
    __syncthreads();

    int base = g * CAP;
    int m = sm_m[0]; if (m > CAP) m = CAP;

    // ---- phase 3: compact copy from node buckets
    for (int n = wid; n < P; n += 8) {
        int deg = sdegc[n], st = sstart[n];
        if (lane < deg) {
            unsigned pk = g_bucket[(size_t)(g * P + n) * BCAP + lane]
                        | ((unsigned)n << 25);
            scsr[st + lane] = pk;
            g_csr[base + st + lane] = pk;
        }
    }
    __syncthreads();

    // ---- phase 4: ea prefetch (float4)
    for (int idx = t; idx < m * 4; idx += 256) {
        int j = idx >> 2, q = idx & 3;
        int eid = scsr[j] & 0xFFFFF;
        ((float4*)sea)[j * 4 + q] = ((const float4*)ea)[eid * 4 + q];
    }
    __syncthreads();

    // ---- phase 5: thread-per-(edge, quad): logit + a2 + sumEA accum
    {
        int oq = t & 7;
        unsigned omask = 0xFFu << ((lane >> 3) * 8);
        const float4* W14 = (const float4*)sWe1;   // k*8 + oq
        const float4* W24 = (const float4*)sWe2;   // k*2 + oq
        for (int j0 = 0; j0 < m; j0 += 32) {
            int j = j0 + (t >> 3);
            if (j < m) {
                unsigned pk = scsr[j];
                int s = (pk >> 20) & 31, d = (pk >> 25) & 31;
                float ev[16];
                *(float4*)(ev)      = ((const float4*)(sea + j * 16))[0];
                *(float4*)(ev + 4)  = ((const float4*)(sea + j * 16))[1];
                *(float4*)(ev + 8)  = ((const float4*)(sea + j * 16))[2];
                *(float4*)(ev + 12) = ((const float4*)(sea + j * 16))[3];
                float4 a = make_float4(0.f, 0.f, 0.f, 0.f);
#pragma unroll
                for (int k = 0; k < 16; k++) {
                    float4 w = W14[k * 8 + oq];
                    a.x += ev[k] * w.x; a.y += ev[k] * w.y;
                    a.z += ev[k] * w.z; a.w += ev[k] * w.w;
                }
                if (oq < 2) {
                    float4 b = make_float4(0.f, 0.f, 0.f, 0.f);
#pragma unroll
                    for (int k = 0; k < 16; k++) {
                        float4 w = W24[k * 2 + oq];
                        b.x += ev[k] * w.x; b.y += ev[k] * w.y;
                        b.z += ev[k] * w.z; b.w += ev[k] * w.w;
                    }
                    *(float4*)(&g_eaWe2[(size_t)(base + j) * H2 + oq * 4]) = b;
                }
                // sumEA accumulation: 2 values per thread (LDS reread avoids
                // dynamic register indexing)
                float2 ev2 = *(const float2*)(sea + j * 16 + oq * 2);
                atomicAdd(&ssumEA[d * 16 + oq * 2 + 0], ev2.x);
                atomicAdd(&ssumEA[d * 16 + oq * 2 + 1], ev2.y);
                float4 xlv = *(const float4*)(sxl + s * 36 + oq * 4);
                float4 xrv = *(const float4*)(sxr + d * 36 + oq * 4);
                float4 atv = *(const float4*)(satt + oq * 4);
                float m0 = xlv.x + xrv.x + a.x, m1 = xlv.y + xrv.y + a.y;
                float m2 = xlv.z + xrv.z + a.z, m3 = xlv.w + xrv.w + a.w;
                float e = (m0 > 0.f ? m0 : 0.2f * m0) * atv.x
                        + (m1 > 0.f ? m1 : 0.2f * m1) * atv.y
                        + (m2 > 0.f ? m2 : 0.2f * m2) * atv.z
                        + (m3 > 0.f ? m3 : 0.2f * m3) * atv.w;
                e += __shfl_xor_sync(omask, e, 1);
                e += __shfl_xor_sync(omask, e, 2);
                e += __shfl_xor_sync(omask, e, 4);
                if (oq == 0) se[j] = e;
            }
        }
    }
    __syncthreads();

    // ---- phase 6: per-node softmax + aggregation (warp per node)
    float st_s = 0.f, st_q = 0.f;
    for (int n = wid; n < P; n += 8) {
        int st = sstart[n], deg = sdegc[n];
        float invd = 1.f / fmaxf((float)deg, 1.f);
        float xln = sxl[n * 36 + lane], xrn = sxr[n * 36 + lane];
        // sum1 = ssumEA[n] @ We1  (broadcast LDS on ssumEA, row reads on We1)
        float sum1 = 0.f;
#pragma unroll
        for (int k = 0; k < 16; k++)
            sum1 += ssumEA[n * 16 + k] * sWe1[k * H1 + lane];
        float mvs = xln + xrn + sum1 * invd;
        float lrs = mvs > 0.f ? mvs : 0.2f * mvs;
        float eps_ = lrs * satt[lane];
#pragma unroll
        for (int o = 16; o; o >>= 1) eps_ += __shfl_xor_sync(0xffffffffu, eps_, o);
        if (lane < 8) {
            float s2 = 0.f;
#pragma unroll
            for (int k = 0; k < 16; k++)
                s2 += ssumEA[n * 16 + k] * sWe2[k * H2 + lane];
            g_selfWe2[(size_t)(g * P + n) * H2 + lane] = s2 * invd;
        }
        float el = (lane < deg) ? se[st + lane] : -1e30f;
        float mx = el;
#pragma unroll
        for (int o = 16; o; o >>= 1) mx = fmaxf(mx, __shfl_xor_sync(0xffffffffu, mx, o));
        mx = fmaxf(mx, eps_);
        float wj = (lane < deg) ? __expf(el - mx) : 0.f;
        float denom = wj;
#pragma unroll
        for (int o = 16; o; o >>= 1) denom += __shfl_xor_sync(0xffffffffu, denom, o);
        float wself = __expf(eps_ - mx);
        denom += wself;
        if (lane < deg) se[st + lane] = wj;
        __syncwarp();
        float acc = wself * xln;
        for (int j = st; j < st + deg; j++) {
            int s = (scsr[j] >> 20) & 31;
            acc += se[j] * sxl[s * 36 + lane];
        }
        float ov = acc / denom + sbo[lane];
        ov = fmaxf(ov, 0.f);
        g_h1[(size_t)(g * P + n) * H1 + lane] = ov;
        st_s += ov; st_q += ov * ov;
    }

    // ---- phase 7: fused BN1 stats
    sred[t] = st_s; __syncthreads();
    if (t < 32) {
        float a = 0.f;
#pragma unroll
        for (int k = 0; k < 8; k++) a += sred[t + 32 * k];
        atomicAdd(&g_sum1[t], (double)a);
    }
    __syncthreads();
    sred[t] = st_q; __syncthreads();
    if (t < 32) {
        float a = 0.f;
#pragma unroll
        for (int k = 0; k < 8; k++) a += sred[t + 32 * k];
        atomicAdd(&g_sq1[t], (double)a);
    }
}

// ============ K3: GATv2 layer 2 ============
__global__ __launch_bounds__(192) void kC(
    const float* __restrict__ Wl2, const float* __restrict__ bl2,
    const float* __restrict__ Wr2, const float* __restrict__ br2,
    const float* __restrict__ att2, const float* __restrict__ bo2,
    const float* __restrict__ g1v, const float* __restrict__ be1)
{
    int g = blockIdx.x;
    int t = threadIdx.x, lane = t & 31;
    int n = t >> 3, l = t & 7;
    unsigned omask = 0xFFu << ((lane >> 3) * 8);

    __shared__ float sh[P * 33];
    __shared__ float sWl[H1 * H2], sWr[H1 * H2];
    __shared__ float sxl[P * 9], sxr[P * 9];
    __shared__ float sa2[CAP * 9];
    __shared__ unsigned scsr[CAP];
    __shared__ float sscale[H1], sbias[H1], satt[H2], sbl[H2], sbr[H2], sbo[H2];
    __shared__ int sdegc[P], sstart[P];
    __shared__ float sred[192];

    if (t < H1) {
        double mu = g_sum1[t] / (double)NN;
        double var = g_sq1[t] / (double)NN - mu * mu;
        float sc = g1v[t] * rsqrtf((float)var + EPSBN);
        sscale[t] = sc;
        sbias[t] = be1[t] - (float)mu * sc;
    }
    for (int i = t; i < H1 * H2; i += 192) { sWl[i] = Wl2[i]; sWr[i] = Wr2[i]; }
    if (t < H2) { satt[t] = att2[t]; sbl[t] = bl2[t]; sbr[t] = br2[t]; sbo[t] = bo2[t]; }
    if (t < P) {
        int d = g_ndeg[g * P + t];
        sdegc[t] = d > BCAP ? BCAP : d;
    }
    __syncthreads();

    int base = g * CAP;
    int m = g_gm[g]; if (m > CAP) m = CAP;

    for (int i = t; i < P * H1; i += 192) {
        int nn = i >> 5, k = i & 31;
        sh[nn * 33 + k] = g_h1[(size_t)g * P * H1 + i] * sscale[k] + sbias[k];
    }
    for (int i = t; i < m; i += 192) scsr[i] = g_csr[base + i];
    for (int i = t; i < m * 2; i += 192) {
        float4 v = ((const float4*)g_eaWe2)[(size_t)base * 2 + i];
        int j = i >> 1, half = (i & 1) * 4;
        sa2[j * 9 + half + 0] = v.x;
        sa2[j * 9 + half + 1] = v.y;
        sa2[j * 9 + half + 2] = v.z;
        sa2[j * 9 + half + 3] = v.w;
    }
    if (t < 32) {
        int v = (lane < P) ? sdegc[lane] : 0;
        int orig = v;
#pragma unroll
        for (int off = 1; off < 32; off <<= 1) {
            int u = __shfl_up_sync(0xffffffffu, v, off);
            if (lane >= off) v += u;
        }
        if (lane < P) sstart[lane] = v - orig;
    }
    __syncthreads();

    {
        float al = sbl[l], ar = sbr[l];
#pragma unroll
        for (int k = 0; k < H1; k++) {
            float v = sh[n * 33 + k];
            al += v * sWl[k * H2 + l];
            ar += v * sWr[k * H2 + l];
        }
        sxl[n * 9 + l] = al; sxr[n * 9 + l] = ar;
    }
    __syncthreads();

    if (t < m) {
        unsigned pk = scsr[t];
        int s = (pk >> 20) & 31, d = (pk >> 25) & 31;
        float e = 0.f;
#pragma unroll
        for (int k = 0; k < H2; k++) {
            float mv = sxl[s * 9 + k] + sxr[d * 9 + k] + sa2[t * 9 + k];
            float lr = mv > 0.f ? mv : 0.2f * mv;
            e += lr * satt[k];
        }
        sa2[t * 9 + 8] = e;
    }
    __syncthreads();

    int st = sstart[n], deg = sdegc[n];
    float xln = sxl[n * 9 + l], xrn = sxr[n * 9 + l];
    float mvs = xln + xrn + g_selfWe2[(size_t)g * P * H2 + t];
    float lrs = mvs > 0.f ? mvs : 0.2f * mvs;
    float eps_ = lrs * satt[l];
    eps_ += __shfl_xor_sync(omask, eps_, 1);
    eps_ += __shfl_xor_sync(omask, eps_, 2);
    eps_ += __shfl_xor_sync(omask, eps_, 4);
    float mx = -1e30f;
    for (int j = st + l; j < st + deg; j += 8) mx = fmaxf(mx, sa2[j * 9 + 8]);
    mx = fmaxf(mx, __shfl_xor_sync(omask, mx, 1));
    mx = fmaxf(mx, __shfl_xor_sync(omask, mx, 2));
    mx = fmaxf(mx, __shfl_xor_sync(omask, mx, 4));
    mx = fmaxf(mx, eps_);
    float denom = 0.f;
    for (int j = st + l; j < st + deg; j += 8) {
        float w = __expf(sa2[j * 9 + 8] - mx);
        sa2[j * 9 + 8] = w;
        denom += w;
    }
    denom += __shfl_xor_sync(omask, denom, 1);
    denom += __shfl_xor_sync(omask, denom, 2);
    denom += __shfl_xor_sync(omask, denom, 4);
    float wself = __expf(eps_ - mx);
    denom += wself;
    __syncwarp();
    float acc = wself * xln;
    for (int j = st; j < st + deg; j++) {
        int s = (scsr[j] >> 20) & 31;
        acc += sa2[j * 9 + 8] * sxl[s * 9 + l];
    }
    float ov = acc / denom + sbo[l];
    ov = 1.f / (1.f + __expf(-ov));
    g_h2[(size_t)g * P * H2 + t] = ov;

    sred[t] = ov; __syncthreads();
    if (t < 8) {
        float a = 0.f;
#pragma unroll
        for (int k = 0; k < 24; k++) a += sred[t + 8 * k];
        atomicAdd(&g_sum2[t], (double)a);
    }
    __syncthreads();
    sred[t] = ov * ov; __syncthreads();
    if (t < 8) {
        float a = 0.f;
#pragma unroll
        for (int k = 0; k < 24; k++) a += sred[t + 8 * k];
        atomicAdd(&g_sq2[t], (double)a);
    }
}

// ============ K4: BN2 + pool + MLP head ============
__global__ __launch_bounds__(256) void kE(
    const float* __restrict__ x,
    const float* __restrict__ g2, const float* __restrict__ be2,
    const float* __restrict__ W1, const float* __restrict__ b1,
    const float* __restrict__ W2, const float* __restrict__ b2,
    const float* __restrict__ W3, const float* __restrict__ b3,
    const float* __restrict__ W4, const float* __restrict__ b4,
    const float* __restrict__ Wo, const float* __restrict__ bo,
    float* __restrict__ out)
{
    int t = threadIdx.x, w = t >> 5, lane = t & 31;
    int g = blockIdx.x * 8 + w;

    __shared__ float sW1[30 * 32], sb1[32], sW2[32 * 16], sb2[16];
    __shared__ float sW3[16 * 8], sb3[8], sW4[8 * 4], sb4[4], sWo[4 * 2], sbo[2];
    __shared__ float sscale[H2], sbias[H2];
    __shared__ float zz[8][90];

    for (int i = t; i < 30 * 32; i += 256) sW1[i] = W1[i];
    for (int i = t; i < 32 * 16; i += 256) sW2[i] = W2[i];
    if (t < 16 * 8) sW3[t] = W3[t];
    if (t < 8 * 4) sW4[t] = W4[t];
    if (t < 8) sWo[t] = Wo[t];
    if (t < 32) sb1[t] = b1[t];
    if (t < 16) sb2[t] = b2[t];
    if (t < 8) sb3[t] = b3[t];
    if (t < 4) sb4[t] = b4[t];
    if (t < 2) sbo[t] = bo[t];
    if (t < H2) {
        double mu = g_sum2[t] / (double)NN;
        double var = g_sq2[t] / (double)NN - mu * mu;
        float sc = g2[t] * rsqrtf((float)var + EPSBN);
        sscale[t] = sc;
        sbias[t] = be2[t] - (float)mu * sc;
    }
    __syncthreads();

    float* z  = zz[w];
    float* z1 = z + 30;
    float* z2 = z1 + 32;
    float* z3 = z2 + 16;
    float* z4 = z3 + 8;

    float acc = 0.f;
    for (int j = lane; j < P * H2; j += 32) {
        int f = j & 7;
        acc += g_h2[(size_t)g * P * H2 + j] * sscale[f] + sbias[f];
    }
    acc += __shfl_xor_sync(0xffffffffu, acc, 8);
    acc += __shfl_xor_sync(0xffffffffu, acc, 16);
    if (lane < 8)  z[lane] = acc * (1.f / 24.f);
    if (lane < 22) z[8 + lane] = x[(size_t)(g * P) * 96 + 74 + lane];
    __syncwarp();

    { float a = sb1[lane];
#pragma unroll
      for (int k = 0; k < 30; k++) a += z[k] * sW1[k * 32 + lane];
      z1[lane] = fmaxf(a, 0.f); }
    __syncwarp();
    if (lane < 16) { float a = sb2[lane];
#pragma unroll
      for (int k = 0; k < 32; k++) a += z1[k] * sW2[k * 16 + lane];
      z2[lane] = fmaxf(a, 0.f); }
    __syncwarp();
    if (lane < 8) { float a = sb3[lane];
#pragma unroll
      for (int k = 0; k < 16; k++) a += z2[k] * sW3[k * 8 + lane];
      z3[lane] = fmaxf(a, 0.f); }
    __syncwarp();
    if (lane < 4) { float a = sb4[lane];
#pragma unroll
      for (int k = 0; k < 8; k++) a += z3[k] * sW4[k * 4 + lane];
      z4[lane] = fmaxf(a, 0.f); }
    __syncwarp();
    if (lane < 2) { float a = sbo[lane];
#pragma unroll
      for (int k = 0; k < 4; k++) a += z4[k] * sWo[k * 2 + lane];
      out[g * 2 + lane] = a; }
}

// ---------------- launch ----------------
extern "C" void kernel_launch(void* const* d_in, const int* in_sizes, int n_in,
                              void* d_out, int out_size)
{
    const float* x    = (const float*)d_in[0];
    const int*   ei   = (const int*)  d_in[1];
    const float* ea   = (const float*)d_in[2];
    const float* Wl1  = (const float*)d_in[4];
    const float* bl1  = (const float*)d_in[5];
    const float* Wr1  = (const float*)d_in[6];
    const float* br1  = (const float*)d_in[7];
    const float* We1  = (const float*)d_in[8];
    const float* att1 = (const float*)d_in[9];
    const float* bo1  = (const float*)d_in[10];
    const float* Wl2  = (const float*)d_in[11];
    const float* bl2  = (const float*)d_in[12];
    const float* Wr2  = (const float*)d_in[13];
    const float* br2  = (const float*)d_in[14];
    const float* We2  = (const float*)d_in[15];
    const float* att2 = (const float*)d_in[16];
    const float* bo2  = (const float*)d_in[17];
    const float* g1   = (const float*)d_in[18];
    const float* be1  = (const float*)d_in[19];
    const float* g2   = (const float*)d_in[20];
    const float* be2  = (const float*)d_in[21];
    const float* fc1W = (const float*)d_in[22];
    const float* fc1b = (const float*)d_in[23];
    const float* fc2W = (const float*)d_in[24];
    const float* fc2b = (const float*)d_in[25];
    const float* fc3W = (const float*)d_in[26];
    const float* fc3b = (const float*)d_in[27];
    const float* fc4W = (const float*)d_in[28];
    const float* fc4b = (const float*)d_in[29];
    const float* outW = (const float*)d_in[30];
    const float* outb = (const float*)d_in[31];

    kZero<<<NN / 256, 256>>>();
    kScatter<<<EE / 256, 256>>>(ei);
    kXlXr<<<NN / 64, 256>>>(x, Wl1, bl1, Wr1, br1);
    kA<<<G, 256>>>(ea, We1, att1, bo1, We2);
    kC<<<G, 192>>>(Wl2, bl2, Wr2, br2, att2, bo2, g1, be1);
    kE<<<G / 8, 256>>>(x, g2, be2, fc1W, fc1b, fc2W, fc2b, fc3W, fc3b,
                       fc4W, fc4b, outW, outb, (float*)d_out);
}